// round 1
// baseline (speedup 1.0000x reference)
#include <cuda_runtime.h>

#define B 256
#define S 2048
#define V 100000
#define E 128

// Scratch: proj[v] = dot(emb[v], fc_w). __device__ global (no cudaMalloc allowed).
__device__ float g_proj[V];

// Kernel 1: one warp per vocab row. Lane l loads float4 of emb row and fc_w,
// dot + warp shuffle reduce. HBM-bound: streams 51.2 MB of emb exactly once.
__global__ void __launch_bounds__(256) proj_kernel(const float* __restrict__ emb,
                                                   const float* __restrict__ fc_w) {
    int gwarp = (blockIdx.x * blockDim.x + threadIdx.x) >> 5;
    int lane = threadIdx.x & 31;
    if (gwarp >= V) return;
    float4 w = reinterpret_cast<const float4*>(fc_w)[lane];
    float4 e = reinterpret_cast<const float4*>(emb + (size_t)gwarp * E)[lane];
    float d = e.x * w.x + e.y * w.y + e.z * w.z + e.w * w.w;
    #pragma unroll
    for (int off = 16; off; off >>= 1)
        d += __shfl_xor_sync(0xffffffffu, d, off);
    if (lane == 0) g_proj[gwarp] = d;
}

// Kernel 2: one block (256 threads) per batch row. int4 text loads (coalesced),
// predicated gather from the L2-resident g_proj table, block reduce.
__global__ void __launch_bounds__(256) pool_kernel(const int* __restrict__ text,
                                                   const int* __restrict__ lengths,
                                                   const float* __restrict__ fc_b,
                                                   float* __restrict__ out) {
    __shared__ float sred[8];
    int b = blockIdx.x;
    int tid = threadIdx.x;
    int len = lengths[b];

    const int4* row = reinterpret_cast<const int4*>(text + (size_t)b * S);
    float acc = 0.0f;
    #pragma unroll
    for (int it = 0; it < (S / 4) / 256; it++) {
        int i = it * 256 + tid;
        int4 t = row[i];
        int s = i * 4;
        if (s + 0 < len) acc += g_proj[t.x];
        if (s + 1 < len) acc += g_proj[t.y];
        if (s + 2 < len) acc += g_proj[t.z];
        if (s + 3 < len) acc += g_proj[t.w];
    }

    // warp reduce
    #pragma unroll
    for (int off = 16; off; off >>= 1)
        acc += __shfl_xor_sync(0xffffffffu, acc, off);
    int lane = tid & 31, warp = tid >> 5;
    if (lane == 0) sred[warp] = acc;
    __syncthreads();
    if (warp == 0) {
        float v = (lane < 8) ? sred[lane] : 0.0f;
        #pragma unroll
        for (int off = 4; off; off >>= 1)
            v += __shfl_xor_sync(0xffffffffu, v, off);
        if (lane == 0)
            out[b] = v / (float)len + fc_b[0];
    }
}

extern "C" void kernel_launch(void* const* d_in, const int* in_sizes, int n_in,
                              void* d_out, int out_size) {
    const int*   text    = (const int*)d_in[0];
    const int*   lengths = (const int*)d_in[1];
    const float* emb     = (const float*)d_in[2];
    const float* fc_w    = (const float*)d_in[3];
    const float* fc_b    = (const float*)d_in[4];
    float* out = (float*)d_out;

    // Kernel 1: 100000 rows, 8 warps (= 8 rows) per 256-thread block.
    int blocks1 = (V + 7) / 8;
    proj_kernel<<<blocks1, 256>>>(emb, fc_w);

    // Kernel 2: one block per batch element.
    pool_kernel<<<B, 256>>>(text, lengths, fc_b, out);
}

// round 2
// speedup vs baseline: 1.1316x; 1.1316x over previous
#include <cuda_runtime.h>

#define B 256
#define S 2048
#define V 100000
#define E 128

// Scratch: proj[v] = dot(emb[v], fc_w). __device__ global (no cudaMalloc allowed).
__device__ float g_proj[V];

// Kernel 1 v2: each warp handles 8 vocab rows. Lane l owns row (l>>2) of the
// group, quarter q=(l&3). It loads 8 independent float4s (32 floats) of its
// row — MLP=8 per lane — FMAs against the preloaded matching fc_w chunks, and
// reduces across only the 4 lanes sharing the row (2 shuffles per 8 rows,
// vs 5 shuffles PER row before).
__global__ void __launch_bounds__(256) proj_kernel(const float* __restrict__ emb,
                                                   const float* __restrict__ fc_w) {
    int lane = threadIdx.x & 31;
    int warp = threadIdx.x >> 5;
    int q = lane & 3;

    // Preload the 8 fc_w float4 chunks this lane will need (columns q+4j).
    float4 w[8];
    #pragma unroll
    for (int j = 0; j < 8; j++)
        w[j] = reinterpret_cast<const float4*>(fc_w)[q + j * 4];

    int row = blockIdx.x * 64 + warp * 8 + (lane >> 2);
    bool valid = (row < V);
    int rowc = valid ? row : (V - 1);  // clamped: keep all lanes converged for shfl

    const float4* rp = reinterpret_cast<const float4*>(emb + (size_t)rowc * E);
    float4 e[8];
    #pragma unroll
    for (int j = 0; j < 8; j++)
        e[j] = rp[q + j * 4];          // 8 independent 16B loads in flight

    float acc = 0.0f;
    #pragma unroll
    for (int j = 0; j < 8; j++) {
        acc = fmaf(e[j].x, w[j].x, acc);
        acc = fmaf(e[j].y, w[j].y, acc);
        acc = fmaf(e[j].z, w[j].z, acc);
        acc = fmaf(e[j].w, w[j].w, acc);
    }

    // Reduce across the 4 lanes sharing this row.
    acc += __shfl_xor_sync(0xffffffffu, acc, 1);
    acc += __shfl_xor_sync(0xffffffffu, acc, 2);

    if (valid && q == 0) g_proj[row] = acc;
}

// Kernel 2 v2: one block of 512 threads per batch row. Each thread handles
// exactly one int4 (4 tokens): a single round of independent L2 gathers, no
// serial loop. 16 warps/block doubles latency-hiding occupancy.
__global__ void __launch_bounds__(512) pool_kernel(const int* __restrict__ text,
                                                   const int* __restrict__ lengths,
                                                   const float* __restrict__ fc_b,
                                                   float* __restrict__ out) {
    __shared__ float sred[16];
    int b = blockIdx.x;
    int tid = threadIdx.x;
    int len = lengths[b];

    int4 t = reinterpret_cast<const int4*>(text + (size_t)b * S)[tid];
    int s = tid * 4;
    float acc = 0.0f;
    if (s + 0 < len) acc += g_proj[t.x];
    if (s + 1 < len) acc += g_proj[t.y];
    if (s + 2 < len) acc += g_proj[t.z];
    if (s + 3 < len) acc += g_proj[t.w];

    // warp reduce
    #pragma unroll
    for (int off = 16; off; off >>= 1)
        acc += __shfl_xor_sync(0xffffffffu, acc, off);
    int lane = tid & 31, warp = tid >> 5;
    if (lane == 0) sred[warp] = acc;
    __syncthreads();
    if (warp == 0) {
        float v = (lane < 16) ? sred[lane] : 0.0f;
        #pragma unroll
        for (int off = 8; off; off >>= 1)
            v += __shfl_xor_sync(0xffffffffu, v, off);
        if (lane == 0)
            out[b] = v / (float)len + fc_b[0];
    }
}

extern "C" void kernel_launch(void* const* d_in, const int* in_sizes, int n_in,
                              void* d_out, int out_size) {
    const int*   text    = (const int*)d_in[0];
    const int*   lengths = (const int*)d_in[1];
    const float* emb     = (const float*)d_in[2];
    const float* fc_w    = (const float*)d_in[3];
    const float* fc_b    = (const float*)d_in[4];
    float* out = (float*)d_out;

    // Kernel 1: 64 rows per 256-thread block (8 warps x 8 rows).
    int blocks1 = (V + 63) / 64;
    proj_kernel<<<blocks1, 256>>>(emb, fc_w);

    // Kernel 2: one 512-thread block per batch element.
    pool_kernel<<<B, 512>>>(text, lengths, fc_b, out);
}